// round 16
// baseline (speedup 1.0000x reference)
#include <cuda_runtime.h>

// DynamicRouting: votes [B=32, NIN=2048, NOUT=64, ATOMS=16] fp32, 3 iterations.
// logits are linear in accumulated pose P:  l = votes . (sum of prior poses)
// Each iteration = one streaming pass over the 256MB votes tensor (proven
// fastest architecture; sync-for-reuse schemes regressed: R4/R5/R6).
//
// R13: (1) L2 prefetch 8 slices ahead of the cp.async pipeline (one 128B-line
// prefetch per lane per mainloop iter = full 4KB slice) -> cp.async completes
// from L2 instead of raw DRAM, deepening effective pipeline 3->8 slices with
// zero smem cost. (2) final_squash at 64 blocks with split capsule/zero work.

#define NB    32
#define NIN   2048
#define NOUT  64
#define ATOMS 16
#define SLICE (NOUT * ATOMS)      // 1024 floats = 4KB per (b,in)
#define GTOT  (NB * NIN)          // 65536 global slices
#define NITER 3

__device__ __align__(256) float g_preact[NITER][NB * SLICE];  // zero at load; squash re-zeros

#define NBLK    592               // 148 SMs x 4 blocks -> exactly one wave
#define WARPS_PB 4
#define NWARPT  (NBLK * WARPS_PB)
#define DEPTH   3
#define PFDIST  8                 // L2 prefetch distance in slices

__device__ __forceinline__ unsigned smem_u32(const void* p) {
    return (unsigned)__cvta_generic_to_shared(p);
}

// One 4KB slice gmem->smem: 8 x 16B per lane, fully coalesced; own commit group.
__device__ __forceinline__ void cp_async_slice(unsigned dst, const float4* __restrict__ src,
                                               int lane) {
#pragma unroll
    for (int j = 0; j < 8; j++) {
        asm volatile("cp.async.cg.shared.global [%0], [%1], 16;\n" ::
                     "r"(dst + (unsigned)(lane + 32 * j) * 16u),
                     "l"(src + lane + 32 * j) : "memory");
    }
    asm volatile("cp.async.commit_group;\n" ::: "memory");
}

__device__ __forceinline__ void cp_async_wait(int n) {
    if (n <= 0)      asm volatile("cp.async.wait_group 0;\n" ::: "memory");
    else if (n == 1) asm volatile("cp.async.wait_group 1;\n" ::: "memory");
    else             asm volatile("cp.async.wait_group 2;\n" ::: "memory");
}

// Emit this warp's accumulator for batch b into g_preact[IT][b] (vector red).
template <int IT>
__device__ __forceinline__ void emit_acc(const float4 acc[8], int b, int lane, float mul) {
    float* out = &g_preact[IT][b * SLICE + 4 * lane];
#pragma unroll
    for (int j = 0; j < 8; j++) {
        asm volatile("red.global.add.v4.f32 [%0], {%1, %2, %3, %4};\n"
                     :: "l"(out + 128 * j),
                        "f"(acc[j].x * mul), "f"(acc[j].y * mul),
                        "f"(acc[j].z * mul), "f"(acc[j].w * mul)
                     : "memory");
    }
}

// P += squash(preact[k][b]) in the lane layout (out = lane/4 + 8j).
__device__ __forceinline__ void add_pose(float4 P[8], const float* __restrict__ pre,
                                         int lane) {
    const float4* p4 = reinterpret_cast<const float4*>(pre);
#pragma unroll
    for (int j = 0; j < 8; j++) {
        float4 pr = p4[lane + 32 * j];
        float sq = pr.x * pr.x + pr.y * pr.y + pr.z * pr.z + pr.w * pr.w;
        sq += __shfl_xor_sync(0xffffffffu, sq, 1);
        sq += __shfl_xor_sync(0xffffffffu, sq, 2);
        float scale = (sq / (1.0f + sq)) * rsqrtf(sq + 1e-9f);
        P[j].x = fmaf(scale, pr.x, P[j].x);
        P[j].y = fmaf(scale, pr.y, P[j].y);
        P[j].z = fmaf(scale, pr.z, P[j].z);
        P[j].w = fmaf(scale, pr.w, P[j].w);
    }
}

template <int ITER>
__device__ __forceinline__ void derive_P(float4 P[8], int b, int lane) {
#pragma unroll
    for (int j = 0; j < 8; j++) P[j] = make_float4(0.f, 0.f, 0.f, 0.f);
#pragma unroll
    for (int k = 0; k < ITER; k++)
        add_pose(P, &g_preact[k][b * SLICE], lane);
}

// Lane layout per slice: lane holds float4 at slice pos 4*lane + 128*j (j=0..7)
// -> out = lane/4 + 8j, atoms 4*(lane&3)..+3.
template <int ITER>
__global__ __launch_bounds__(128, 4) void route_kernel(const float* __restrict__ votes) {
    __shared__ float stage[WARPS_PB][DEPTH][SLICE];   // 48KB

    const int lane = threadIdx.x & 31;
    const int warp = threadIdx.x >> 5;
    const int wid  = blockIdx.x * WARPS_PB + warp;    // 0..2367

    // contiguous global slice range for this warp (~27-28 slices)
    const int wlo = (int)(((long long)wid * GTOT) / NWARPT);
    const int whi = (int)(((long long)(wid + 1) * GTOT) / NWARPT);
    const int n   = whi - wlo;

    const float4* V = reinterpret_cast<const float4*>(votes);

    unsigned sbase[DEPTH];
#pragma unroll
    for (int d = 0; d < DEPTH; d++) sbase[d] = smem_u32(&stage[warp][d][0]);

    // prologue: fill cp.async pipeline + prime L2 prefetch window
    int committed = 0;
#pragma unroll
    for (int k = 0; k < DEPTH; k++)
        if (k < n) { cp_async_slice(sbase[k], V + (size_t)(wlo + k) * (SLICE / 4), lane); committed++; }
#pragma unroll
    for (int k = DEPTH; k < PFDIST; k++) {
        if (k < n) {
            const char* pf = (const char*)(V + (size_t)(wlo + k) * (SLICE / 4)) + lane * 128;
            asm volatile("prefetch.global.L2 [%0];\n" :: "l"(pf));
        }
    }

    int cur_b = wlo >> 11;           // NIN = 2048
    float4 P[8];
    derive_P<ITER>(P, cur_b, lane);  // no-op loads for ITER==0

    float4 acc[8];
#pragma unroll
    for (int j = 0; j < 8; j++) acc[j] = make_float4(0.f, 0.f, 0.f, 0.f);

    const float umul = (ITER == 0) ? (1.0f / NOUT) : 1.0f;

    for (int i = 0; i < n; i++) {
        const int gs = wlo + i;
        const int b  = gs >> 11;
        if (b != cur_b) {            // at most once per warp
            emit_acc<ITER>(acc, cur_b, lane, umul);
#pragma unroll
            for (int j = 0; j < 8; j++) acc[j] = make_float4(0.f, 0.f, 0.f, 0.f);
            cur_b = b;
            derive_P<ITER>(P, cur_b, lane);
        }

        // L2 prefetch PFDIST slices ahead: 32 lanes x 128B = whole 4KB slice
        if (i + PFDIST < n) {
            const char* pf = (const char*)(V + (size_t)(gs + PFDIST) * (SLICE / 4)) + lane * 128;
            asm volatile("prefetch.global.L2 [%0];\n" :: "l"(pf));
        }

        cp_async_wait(committed - i - 1);

        const float4* sv = reinterpret_cast<const float4*>(&stage[warp][i % DEPTH][0]);
        float4 v[8];
#pragma unroll
        for (int j = 0; j < 8; j++) v[j] = sv[lane + 32 * j];

        if (i + DEPTH < n) {
            cp_async_slice(sbase[i % DEPTH], V + (size_t)(gs + DEPTH) * (SLICE / 4), lane);
            committed++;
        }

        if (ITER == 0) {
            // softmax(0) = uniform 1/NOUT: plain sum, scaled at emit
#pragma unroll
            for (int j = 0; j < 8; j++) {
                acc[j].x += v[j].x; acc[j].y += v[j].y;
                acc[j].z += v[j].z; acc[j].w += v[j].w;
            }
        } else {
            // logits: 16-atom dot via 4-lane xor reduce (4 lanes share one out)
            float l[8];
#pragma unroll
            for (int j = 0; j < 8; j++) {
                float d = v[j].x * P[j].x + v[j].y * P[j].y
                        + v[j].z * P[j].z + v[j].w * P[j].w;
                d += __shfl_xor_sync(0xffffffffu, d, 1);
                d += __shfl_xor_sync(0xffffffffu, d, 2);
                l[j] = d;
            }
            // softmax over 64 outs, no max shift (|l| small, fp32-safe)
            float s = 0.f;
#pragma unroll
            for (int j = 0; j < 8; j++) { l[j] = __expf(l[j]); s += l[j]; }
            s += __shfl_xor_sync(0xffffffffu, s, 4);
            s += __shfl_xor_sync(0xffffffffu, s, 8);
            s += __shfl_xor_sync(0xffffffffu, s, 16);
            float inv = 1.0f / s;
#pragma unroll
            for (int j = 0; j < 8; j++) {
                float c = l[j] * inv;
                acc[j].x = fmaf(c, v[j].x, acc[j].x);
                acc[j].y = fmaf(c, v[j].y, acc[j].y);
                acc[j].z = fmaf(c, v[j].z, acc[j].z);
                acc[j].w = fmaf(c, v[j].w, acc[j].w);
            }
        }
    }
    emit_acc<ITER>(acc, cur_b, lane, umul);
}

// Final: pose = squash(preact[2]) -> outputs; re-zero ALL preact buffers
// (graph-replay self-restore). 64 blocks: first 8192 threads do capsules
// (4 threads/capsule, coalesced float4); all 16384 share the zeroing.
#define SQ_THREADS 256
#define SQ_BLOCKS  64
__global__ void final_squash_kernel(float* __restrict__ d_out) {
    const int tid = blockIdx.x * SQ_THREADS + threadIdx.x;    // 0..16383

    if (tid < 4 * NB * NOUT) {
        const int cap  = tid >> 2;       // capsule index (b*NOUT + out)
        const int part = tid & 3;        // which float4 of the 16 atoms

        const float4* pre4 = reinterpret_cast<const float4*>(&g_preact[NITER - 1][cap * ATOMS]);
        float4 pr = pre4[part];
        float sq = pr.x * pr.x + pr.y * pr.y + pr.z * pr.z + pr.w * pr.w;
        sq += __shfl_xor_sync(0xffffffffu, sq, 1);
        sq += __shfl_xor_sync(0xffffffffu, sq, 2);

        float scale = (sq / (1.0f + sq)) * rsqrtf(sq + 1e-9f);

        float4* out4 = reinterpret_cast<float4*>(d_out + cap * ATOMS);
        out4[part] = make_float4(pr.x * scale, pr.y * scale, pr.z * scale, pr.w * scale);
        if (part == 0) {
            float psq = scale * scale * sq;                       // sum(pose^2)
            d_out[NB * NOUT * ATOMS + cap] = sqrtf(psq + 1e-9f);  // prob_out [B, NOUT]
        }
    }

    // re-zero all preact buffers: 3*32768 float4s over 16384 threads = 6 each
    float4* pz = reinterpret_cast<float4*>(&g_preact[0][0]);
#pragma unroll
    for (int k = 0; k < (NITER * NB * SLICE / 4) / (SQ_BLOCKS * SQ_THREADS); k++)
        pz[tid + k * SQ_BLOCKS * SQ_THREADS] = make_float4(0.f, 0.f, 0.f, 0.f);
}

extern "C" void kernel_launch(void* const* d_in, const int* in_sizes, int n_in,
                              void* d_out, int out_size) {
    const float* votes = (const float*)d_in[0];
    float* out = (float*)d_out;

    route_kernel<0><<<NBLK, 128>>>(votes);
    route_kernel<1><<<NBLK, 128>>>(votes);
    route_kernel<2><<<NBLK, 128>>>(votes);
    final_squash_kernel<<<SQ_BLOCKS, SQ_THREADS>>>(out);
}

// round 17
// speedup vs baseline: 1.2452x; 1.2452x over previous
#include <cuda_runtime.h>

// DynamicRouting: votes [B=32, NIN=2048, NOUT=64, ATOMS=16] fp32, 3 iterations.
// logits are linear in accumulated pose P:  l = votes . (sum of prior poses)
// Each iteration = one streaming pass over the 256MB votes tensor (proven
// fastest architecture; sync-for-reuse schemes regressed R4/R5/R6; L2
// prefetch regressed R13-R16 -> mainloop memory mix is frozen at R12).
//
// R17 = R12 + PDL: route<1>, route<2>, final_squash launch with programmatic
// stream serialization. Their votes-only cp.async prologue runs in the
// predecessor's tail shadow; cudaGridDependencySynchronize() guards the first
// preact read. Predecessors trigger launch completion right after their last
// emission. DRAM stays fed across kernel boundaries.

#define NB    32
#define NIN   2048
#define NOUT  64
#define ATOMS 16
#define SLICE (NOUT * ATOMS)      // 1024 floats = 4KB per (b,in)
#define GTOT  (NB * NIN)          // 65536 global slices
#define NITER 3

__device__ __align__(256) float g_preact[NITER][NB * SLICE];  // zero at load; squash re-zeros

#define NBLK    592               // 148 SMs x 4 blocks -> exactly one wave
#define WARPS_PB 4
#define NWARPT  (NBLK * WARPS_PB)
#define DEPTH   3

__device__ __forceinline__ unsigned smem_u32(const void* p) {
    return (unsigned)__cvta_generic_to_shared(p);
}

// One 4KB slice gmem->smem: 8 x 16B per lane, fully coalesced; own commit group.
__device__ __forceinline__ void cp_async_slice(unsigned dst, const float4* __restrict__ src,
                                               int lane) {
#pragma unroll
    for (int j = 0; j < 8; j++) {
        asm volatile("cp.async.cg.shared.global [%0], [%1], 16;\n" ::
                     "r"(dst + (unsigned)(lane + 32 * j) * 16u),
                     "l"(src + lane + 32 * j) : "memory");
    }
    asm volatile("cp.async.commit_group;\n" ::: "memory");
}

__device__ __forceinline__ void cp_async_wait(int n) {
    if (n <= 0)      asm volatile("cp.async.wait_group 0;\n" ::: "memory");
    else if (n == 1) asm volatile("cp.async.wait_group 1;\n" ::: "memory");
    else             asm volatile("cp.async.wait_group 2;\n" ::: "memory");
}

// Emit this warp's accumulator for batch b into g_preact[IT][b] (vector red).
template <int IT>
__device__ __forceinline__ void emit_acc(const float4 acc[8], int b, int lane, float mul) {
    float* out = &g_preact[IT][b * SLICE + 4 * lane];
#pragma unroll
    for (int j = 0; j < 8; j++) {
        asm volatile("red.global.add.v4.f32 [%0], {%1, %2, %3, %4};\n"
                     :: "l"(out + 128 * j),
                        "f"(acc[j].x * mul), "f"(acc[j].y * mul),
                        "f"(acc[j].z * mul), "f"(acc[j].w * mul)
                     : "memory");
    }
}

// P += squash(preact[k][b]) in the lane layout (out = lane/4 + 8j).
__device__ __forceinline__ void add_pose(float4 P[8], const float* __restrict__ pre,
                                         int lane) {
    const float4* p4 = reinterpret_cast<const float4*>(pre);
#pragma unroll
    for (int j = 0; j < 8; j++) {
        float4 pr = p4[lane + 32 * j];
        float sq = pr.x * pr.x + pr.y * pr.y + pr.z * pr.z + pr.w * pr.w;
        sq += __shfl_xor_sync(0xffffffffu, sq, 1);
        sq += __shfl_xor_sync(0xffffffffu, sq, 2);
        float scale = (sq / (1.0f + sq)) * rsqrtf(sq + 1e-9f);
        P[j].x = fmaf(scale, pr.x, P[j].x);
        P[j].y = fmaf(scale, pr.y, P[j].y);
        P[j].z = fmaf(scale, pr.z, P[j].z);
        P[j].w = fmaf(scale, pr.w, P[j].w);
    }
}

template <int ITER>
__device__ __forceinline__ void derive_P(float4 P[8], int b, int lane) {
#pragma unroll
    for (int j = 0; j < 8; j++) P[j] = make_float4(0.f, 0.f, 0.f, 0.f);
#pragma unroll
    for (int k = 0; k < ITER; k++)
        add_pose(P, &g_preact[k][b * SLICE], lane);
}

// Lane layout per slice: lane holds float4 at slice pos 4*lane + 128*j (j=0..7)
// -> out = lane/4 + 8j, atoms 4*(lane&3)..+3.
template <int ITER>
__global__ __launch_bounds__(128, 4) void route_kernel(const float* __restrict__ votes) {
    __shared__ float stage[WARPS_PB][DEPTH][SLICE];   // 48KB

    const int lane = threadIdx.x & 31;
    const int warp = threadIdx.x >> 5;
    const int wid  = blockIdx.x * WARPS_PB + warp;    // 0..2367

    // contiguous global slice range for this warp (~27-28 slices)
    const int wlo = (int)(((long long)wid * GTOT) / NWARPT);
    const int whi = (int)(((long long)(wid + 1) * GTOT) / NWARPT);
    const int n   = whi - wlo;

    const float4* V = reinterpret_cast<const float4*>(votes);

    unsigned sbase[DEPTH];
#pragma unroll
    for (int d = 0; d < DEPTH; d++) sbase[d] = smem_u32(&stage[warp][d][0]);

    // prologue: fill pipeline (votes only -> legal before griddepsync)
    int committed = 0;
#pragma unroll
    for (int k = 0; k < DEPTH; k++)
        if (k < n) { cp_async_slice(sbase[k], V + (size_t)(wlo + k) * (SLICE / 4), lane); committed++; }

    // PDL: wait for the predecessor pass before any preact read
    if (ITER > 0) cudaGridDependencySynchronize();

    int cur_b = wlo >> 11;           // NIN = 2048
    float4 P[8];
    derive_P<ITER>(P, cur_b, lane);  // no-op loads for ITER==0

    float4 acc[8];
#pragma unroll
    for (int j = 0; j < 8; j++) acc[j] = make_float4(0.f, 0.f, 0.f, 0.f);

    const float umul = (ITER == 0) ? (1.0f / NOUT) : 1.0f;

    for (int i = 0; i < n; i++) {
        const int gs = wlo + i;
        const int b  = gs >> 11;
        if (b != cur_b) {            // at most once per warp
            emit_acc<ITER>(acc, cur_b, lane, umul);
#pragma unroll
            for (int j = 0; j < 8; j++) acc[j] = make_float4(0.f, 0.f, 0.f, 0.f);
            cur_b = b;
            derive_P<ITER>(P, cur_b, lane);
        }

        cp_async_wait(committed - i - 1);

        const float4* sv = reinterpret_cast<const float4*>(&stage[warp][i % DEPTH][0]);
        float4 v[8];
#pragma unroll
        for (int j = 0; j < 8; j++) v[j] = sv[lane + 32 * j];

        if (i + DEPTH < n) {
            cp_async_slice(sbase[i % DEPTH], V + (size_t)(gs + DEPTH) * (SLICE / 4), lane);
            committed++;
        }

        if (ITER == 0) {
            // softmax(0) = uniform 1/NOUT: plain sum, scaled at emit
#pragma unroll
            for (int j = 0; j < 8; j++) {
                acc[j].x += v[j].x; acc[j].y += v[j].y;
                acc[j].z += v[j].z; acc[j].w += v[j].w;
            }
        } else {
            // logits: 16-atom dot via 4-lane xor reduce (4 lanes share one out)
            float l[8];
#pragma unroll
            for (int j = 0; j < 8; j++) {
                float d = v[j].x * P[j].x + v[j].y * P[j].y
                        + v[j].z * P[j].z + v[j].w * P[j].w;
                d += __shfl_xor_sync(0xffffffffu, d, 1);
                d += __shfl_xor_sync(0xffffffffu, d, 2);
                l[j] = d;
            }
            // softmax over 64 outs, no max shift (|l| small, fp32-safe)
            float s = 0.f;
#pragma unroll
            for (int j = 0; j < 8; j++) { l[j] = __expf(l[j]); s += l[j]; }
            s += __shfl_xor_sync(0xffffffffu, s, 4);
            s += __shfl_xor_sync(0xffffffffu, s, 8);
            s += __shfl_xor_sync(0xffffffffu, s, 16);
            float inv = 1.0f / s;
#pragma unroll
            for (int j = 0; j < 8; j++) {
                float c = l[j] * inv;
                acc[j].x = fmaf(c, v[j].x, acc[j].x);
                acc[j].y = fmaf(c, v[j].y, acc[j].y);
                acc[j].z = fmaf(c, v[j].z, acc[j].z);
                acc[j].w = fmaf(c, v[j].w, acc[j].w);
            }
        }
    }
    emit_acc<ITER>(acc, cur_b, lane, umul);

    // PDL: this block's emissions are done -> let the dependent grid ramp up
    cudaTriggerProgrammaticLaunchCompletion();
}

// Final: pose = squash(preact[2]) -> outputs; re-zero ALL preact buffers
// (graph-replay self-restore). 4 threads/capsule, coalesced float4 loads.
#define SQ_THREADS 256
#define SQ_BLOCKS  32          // 32*256 = 8192 = 4 * 2048 capsules
__global__ void final_squash_kernel(float* __restrict__ d_out) {
    cudaGridDependencySynchronize();   // wait for route<2> emissions

    const int tid  = blockIdx.x * SQ_THREADS + threadIdx.x;   // 0..8191
    const int cap  = tid >> 2;           // capsule index (b*NOUT + out)
    const int part = tid & 3;            // which float4 of the 16 atoms

    const float4* pre4 = reinterpret_cast<const float4*>(&g_preact[NITER - 1][cap * ATOMS]);
    float4 pr = pre4[part];
    float sq = pr.x * pr.x + pr.y * pr.y + pr.z * pr.z + pr.w * pr.w;
    sq += __shfl_xor_sync(0xffffffffu, sq, 1);
    sq += __shfl_xor_sync(0xffffffffu, sq, 2);

    float scale = (sq / (1.0f + sq)) * rsqrtf(sq + 1e-9f);

    float4* out4 = reinterpret_cast<float4*>(d_out + cap * ATOMS);
    out4[part] = make_float4(pr.x * scale, pr.y * scale, pr.z * scale, pr.w * scale);
    if (part == 0) {
        float psq = scale * scale * sq;                       // sum(pose^2)
        d_out[NB * NOUT * ATOMS + cap] = sqrtf(psq + 1e-9f);  // prob_out [B, NOUT]
    }

    // re-zero all preact buffers: 3*32768 float4s over 8192 threads = 12 each
    float4* pz = reinterpret_cast<float4*>(&g_preact[0][0]);
#pragma unroll
    for (int k = 0; k < (NITER * NB * SLICE / 4) / (SQ_BLOCKS * SQ_THREADS); k++)
        pz[tid + k * SQ_BLOCKS * SQ_THREADS] = make_float4(0.f, 0.f, 0.f, 0.f);
}

extern "C" void kernel_launch(void* const* d_in, const int* in_sizes, int n_in,
                              void* d_out, int out_size) {
    const float* votes = (const float*)d_in[0];
    float* out = (float*)d_out;

    // route<0>: ordinary launch (graph edge orders it after prior replay)
    route_kernel<0><<<NBLK, 128>>>(votes);

    // dependents launch with programmatic stream serialization (PDL)
    cudaLaunchAttribute attr[1];
    attr[0].id = cudaLaunchAttributeProgrammaticStreamSerialization;
    attr[0].val.programmaticStreamSerializationAllowed = 1;

    cudaLaunchConfig_t cfg = {};
    cfg.gridDim  = dim3(NBLK, 1, 1);
    cfg.blockDim = dim3(128, 1, 1);
    cfg.dynamicSmemBytes = 0;
    cfg.attrs = attr;
    cfg.numAttrs = 1;

    cudaLaunchKernelEx(&cfg, route_kernel<1>, votes);
    cudaLaunchKernelEx(&cfg, route_kernel<2>, votes);

    cudaLaunchConfig_t scfg = {};
    scfg.gridDim  = dim3(SQ_BLOCKS, 1, 1);
    scfg.blockDim = dim3(SQ_THREADS, 1, 1);
    scfg.dynamicSmemBytes = 0;
    scfg.attrs = attr;
    scfg.numAttrs = 1;

    cudaLaunchKernelEx(&scfg, final_squash_kernel, out);
}